// round 6
// baseline (speedup 1.0000x reference)
#include <cuda_runtime.h>

// Block_line4feature: 4 fixed depthwise 3x3 convs + weighted affine sum + InstanceNorm2d
// collapses to ONE 3x3 stencil + per-image normalization:
//   conv = x*K,  K = [[-4,-2,-1],[-0.5,15,-0.5],[-1,-2,-4]]/15  (zero padding)
//   out  = (conv - mean_img(conv)) * rsqrt(var_img(conv) + 4e-5)
// Input x: [32,4,512,512] f32 -> 128 independent 512x512 images.
//
// Pass 1: stencil + per-block partial sum/sumsq (deterministic, no atomics)
// Stats : 128 threads fold 4 partials/image -> mean, rstd
// Pass 2: stencil recompute + normalize + store (saves 128MB vs materializing conv)

#define IMG_H 512
#define IMG_W 512
#define N_IMG 128
#define PX_PER_IMG (IMG_H * IMG_W)

#define WARPS_PER_BLOCK 4
#define ROWS_PER_WARP 32
#define WARPS_PER_IMG (IMG_H / ROWS_PER_WARP)               // 16
#define BLOCKS_PER_IMG (WARPS_PER_IMG / WARPS_PER_BLOCK)    // 4
#define GRID_BLOCKS (N_IMG * BLOCKS_PER_IMG)                // 512

__device__ float g_psum[GRID_BLOCKS];
__device__ float g_psumsq[GRID_BLOCKS];
__device__ float g_mean[N_IMG];
__device__ float g_rstd[N_IMG];

struct RowBuf {
    union { float4 q[4]; float f[16]; };
    float l, r;   // left (col-1) and right (col+16) neighbor values
};

__device__ __forceinline__ void zero_row(RowBuf& b) {
#pragma unroll
    for (int g = 0; g < 4; ++g) b.q[g] = make_float4(0.f, 0.f, 0.f, 0.f);
    b.l = 0.f; b.r = 0.f;
}

// Warp covers one full 512-wide row: lane handles cols [16*lane, 16*lane+16).
// Horizontal neighbors across lanes via 2 shuffles; image edges are zero padding.
__device__ __forceinline__ void load_row(RowBuf& b, const float* __restrict__ rowp, int lane) {
    const float4* p4 = reinterpret_cast<const float4*>(rowp) + lane * 4;
#pragma unroll
    for (int g = 0; g < 4; ++g) b.q[g] = p4[g];
    float lv = __shfl_up_sync(0xffffffffu, b.f[15], 1);
    b.l = (lane == 0) ? 0.f : lv;
    float rv = __shfl_down_sync(0xffffffffu, b.f[0], 1);
    b.r = (lane == 31) ? 0.f : rv;
}

// 9-point stencil for 16 pixels. P=row r-1, C=row r, N=row r+1.
__device__ __forceinline__ void conv_row(const RowBuf& P, const RowBuf& C, const RowBuf& N,
                                         float out[16]) {
    const float cA = -4.0f / 15.0f;   // main-diag corners: (r-1,c-1), (r+1,c+1)
    const float cB = -2.0f / 15.0f;   // vertical: (r-1,c), (r+1,c)
    const float cC = -1.0f / 15.0f;   // anti-diag corners: (r-1,c+1), (r+1,c-1)
    const float cD = -1.0f / 30.0f;   // horizontal: (r,c-1), (r,c+1)
#pragma unroll
    for (int k = 0; k < 16; ++k) {
        float pl = (k == 0)  ? P.l : P.f[k - 1];
        float pr = (k == 15) ? P.r : P.f[k + 1];
        float cl = (k == 0)  ? C.l : C.f[k - 1];
        float cr = (k == 15) ? C.r : C.f[k + 1];
        float nl = (k == 0)  ? N.l : N.f[k - 1];
        float nr = (k == 15) ? N.r : N.f[k + 1];
        float v = C.f[k];
        v = fmaf(cA, pl + nr, v);
        v = fmaf(cB, P.f[k] + N.f[k], v);
        v = fmaf(cC, pr + nl, v);
        v = fmaf(cD, cl + cr, v);
        out[k] = v;
    }
}

// ---------------- Pass 1: stencil + per-block stats ----------------

#define STEP1(Pb, Cb, Nb, rr) do {                                              \
    if ((rr) + 1 < IMG_H) load_row(Nb, base + ((rr) + 1) * IMG_W, lane);        \
    else                  zero_row(Nb);                                         \
    float cv[16];                                                               \
    conv_row(Pb, Cb, Nb, cv);                                                   \
    _Pragma("unroll")                                                           \
    for (int k = 0; k < 16; ++k) { s += cv[k]; s2 = fmaf(cv[k], cv[k], s2); }   \
} while (0)

__global__ __launch_bounds__(128, 4) void pass1_kernel(const float* __restrict__ x) {
    const int lane = threadIdx.x & 31;
    const int warp = threadIdx.x >> 5;
    const int gw = blockIdx.x * WARPS_PER_BLOCK + warp;
    const int img = gw / WARPS_PER_IMG;
    const int r0 = (gw % WARPS_PER_IMG) * ROWS_PER_WARP;
    const float* base = x + (size_t)img * PX_PER_IMG;

    RowBuf A, B, C;
    if (r0 == 0) zero_row(A);
    else         load_row(A, base + (r0 - 1) * IMG_W, lane);
    load_row(B, base + r0 * IMG_W, lane);

    float s = 0.f, s2 = 0.f;
#pragma unroll 1
    for (int r = r0; r < r0 + 30; r += 3) {
        STEP1(A, B, C, r);
        STEP1(B, C, A, r + 1);
        STEP1(C, A, B, r + 2);
    }
    // 32 rows = 10*3 + 2; after 10 rotations roles are back to (A=prev, B=cur)
    STEP1(A, B, C, r0 + 30);
    STEP1(B, C, A, r0 + 31);

    // warp reduce (fixed butterfly order -> deterministic)
#pragma unroll
    for (int off = 16; off > 0; off >>= 1) {
        s  += __shfl_xor_sync(0xffffffffu, s,  off);
        s2 += __shfl_xor_sync(0xffffffffu, s2, off);
    }

    __shared__ float sh_s[WARPS_PER_BLOCK], sh_s2[WARPS_PER_BLOCK];
    if (lane == 0) { sh_s[warp] = s; sh_s2[warp] = s2; }
    __syncthreads();
    if (threadIdx.x == 0) {
        float bs = 0.f, bs2 = 0.f;
#pragma unroll
        for (int w = 0; w < WARPS_PER_BLOCK; ++w) { bs += sh_s[w]; bs2 += sh_s2[w]; }
        g_psum[blockIdx.x] = bs;
        g_psumsq[blockIdx.x] = bs2;
    }
}

// ---------------- Stats: fold 4 partials per image ----------------

__global__ void stats_kernel() {
    int img = threadIdx.x;
    if (img >= N_IMG) return;
    float s = 0.f, s2 = 0.f;
#pragma unroll
    for (int b = 0; b < BLOCKS_PER_IMG; ++b) {
        s  += g_psum[img * BLOCKS_PER_IMG + b];
        s2 += g_psumsq[img * BLOCKS_PER_IMG + b];
    }
    const float inv_n = 1.0f / (float)PX_PER_IMG;
    float mean = s * inv_n;
    float var = fmaf(s2, inv_n, -mean * mean);
    g_mean[img] = mean;
    g_rstd[img] = rsqrtf(var + 4e-5f);   // 4 * InstanceNorm eps (1e-5), from affine fold
}

// ---------------- Pass 2: stencil recompute + normalize + store ----------------

#define STEP2(Pb, Cb, Nb, rr) do {                                              \
    if ((rr) + 1 < IMG_H) load_row(Nb, base + ((rr) + 1) * IMG_W, lane);        \
    else                  zero_row(Nb);                                         \
    float cv[16];                                                               \
    conv_row(Pb, Cb, Nb, cv);                                                   \
    float4* op = reinterpret_cast<float4*>(obase + (rr) * IMG_W) + lane * 4;    \
    _Pragma("unroll")                                                           \
    for (int g = 0; g < 4; ++g) {                                               \
        float4 o;                                                               \
        o.x = (cv[4 * g + 0] - mean) * rstd;                                    \
        o.y = (cv[4 * g + 1] - mean) * rstd;                                    \
        o.z = (cv[4 * g + 2] - mean) * rstd;                                    \
        o.w = (cv[4 * g + 3] - mean) * rstd;                                    \
        op[g] = o;                                                              \
    }                                                                           \
} while (0)

__global__ __launch_bounds__(128, 4) void pass2_kernel(const float* __restrict__ x,
                                                       float* __restrict__ out) {
    const int lane = threadIdx.x & 31;
    const int gw = blockIdx.x * WARPS_PER_BLOCK + (threadIdx.x >> 5);
    const int img = gw / WARPS_PER_IMG;
    const int r0 = (gw % WARPS_PER_IMG) * ROWS_PER_WARP;
    const float* base = x + (size_t)img * PX_PER_IMG;
    float* obase = out + (size_t)img * PX_PER_IMG;

    const float mean = g_mean[img];
    const float rstd = g_rstd[img];

    RowBuf A, B, C;
    if (r0 == 0) zero_row(A);
    else         load_row(A, base + (r0 - 1) * IMG_W, lane);
    load_row(B, base + r0 * IMG_W, lane);

#pragma unroll 1
    for (int r = r0; r < r0 + 30; r += 3) {
        STEP2(A, B, C, r);
        STEP2(B, C, A, r + 1);
        STEP2(C, A, B, r + 2);
    }
    STEP2(A, B, C, r0 + 30);
    STEP2(B, C, A, r0 + 31);
}

extern "C" void kernel_launch(void* const* d_in, const int* in_sizes, int n_in,
                              void* d_out, int out_size) {
    const float* x = (const float*)d_in[0];
    float* out = (float*)d_out;
    (void)in_sizes; (void)n_in; (void)out_size;

    pass1_kernel<<<GRID_BLOCKS, 128>>>(x);
    stats_kernel<<<1, 128>>>();
    pass2_kernel<<<GRID_BLOCKS, 128>>>(x, out);
}